// round 14
// baseline (speedup 1.0000x reference)
#include <cuda_runtime.h>
#include <math.h>

#define Bb  2
#define Tt  32
#define Hh  64
#define Ww  64
#define Cc  32
#define KSZ 15
#define WR  33          // W/2 + 1
#define PAD 24          // (64-15)//2
#define PITCH 70        // smem row pitch in float2

// ---------------- scratch (device globals: allocation-free) ----------------
__device__ float2 d_U[Bb*Tt*Cc*Hh*WR];   // U_hat, overwritten with Y_hat in scan
__device__ float2 d_V[Bb*Tt*(Cc/2)*Hh*Ww]; // pair-packed planes (fwd staging / inv result)
__device__ float2 d_KE[Cc*Hh*WR];
__device__ float2 d_KI[Cc*Hh*WR];
__device__ float  d_gates[4][Bb*Tt*Cc];  // alpha, delta, mu, gamma
__device__ float  d_ctx[Bb*Tt*Cc];       // spatial means (from FFT DC bin)

// ---------------- complex helpers ----------------
__device__ __forceinline__ float2 cadd(float2 a, float2 b){ return make_float2(a.x+b.x, a.y+b.y); }
__device__ __forceinline__ float2 csub(float2 a, float2 b){ return make_float2(a.x-b.x, a.y-b.y); }
__device__ __forceinline__ float2 cmul(float2 a, float2 b){
    return make_float2(a.x*b.x - a.y*b.y, a.x*b.y + a.y*b.x);
}

// 8-pt DIF FFT in registers. DIR=-1 fwd, +1 inv. Output bit-reversed:
// X[k] = v[rev(k)], rev = {0,4,2,6,1,5,3,7}.
template<int DIR>
__device__ __forceinline__ void fft8r(float2 v[8]) {
    const float s = 0.70710678118654752f;
    float2 t0=csub(v[0],v[4]), t1=csub(v[1],v[5]), t2=csub(v[2],v[6]), t3=csub(v[3],v[7]);
    v[0]=cadd(v[0],v[4]); v[1]=cadd(v[1],v[5]); v[2]=cadd(v[2],v[6]); v[3]=cadd(v[3],v[7]);
    v[4]=t0;
    v[5]=cmul(t1, make_float2(s, (float)DIR*s));
    v[6]=make_float2(-(float)DIR*t2.y, (float)DIR*t2.x);
    v[7]=cmul(t3, make_float2(-s, (float)DIR*s));
    #pragma unroll
    for (int o=0;o<8;o+=4){
        float2 a=v[o],   b=v[o+2]; v[o]  =cadd(a,b); float2 d0=csub(a,b);
        float2 c=v[o+1], d=v[o+3]; v[o+1]=cadd(c,d); float2 d1=csub(c,d);
        v[o+2]=d0;
        v[o+3]=make_float2(-(float)DIR*d1.y, (float)DIR*d1.x);
    }
    #pragma unroll
    for (int o=0;o<8;o+=2){
        float2 a=v[o], b=v[o+1]; v[o]=cadd(a,b); v[o+1]=csub(a,b);
    }
}

// 64-pt FFT over one line, by an 8-lane octet. smem touched only at load+store;
// the middle transpose is register-resident via shfl_xor within the octet.
template<int DIR, int STRIDE>
__device__ __forceinline__ void fft64_line(float2* base, int lane, float2 wstep)
{
    constexpr int rv[8] = {0,4,2,6,1,5,3,7};
    float2 v[8];
    #pragma unroll
    for (int n=0;n<8;n++) v[n] = base[(8*n+lane)*STRIDE];
    fft8r<DIR>(v);
    float2 w[8];
    w[0] = v[0];                       // rv[0]=0, twiddle^0
    float2 t = wstep;
    w[1] = cmul(v[rv[1]], t);
    #pragma unroll
    for (int k=2;k<8;k++){ t = cmul(t, wstep); w[k] = cmul(v[rv[k]], t); }
    // 8x8 octet transpose (Eklundh): out[reg r][lane l] = in[reg l][lane r]
    #pragma unroll
    for (int s=1;s<8;s<<=1){
        #pragma unroll
        for (int k=0;k<8;k++){
            if ((k & s) == 0){
                float2 give = (lane & s) ? w[k] : w[k|s];
                float2 got;
                got.x = __shfl_xor_sync(0xffffffffu, give.x, s);
                got.y = __shfl_xor_sync(0xffffffffu, give.y, s);
                if (lane & s) w[k] = got; else w[k|s] = got;
            }
        }
    }
    fft8r<DIR>(w);
    #pragma unroll
    for (int k=0;k<8;k++) base[(8*k+lane)*STRIDE] = w[rv[k]];
}

// full in-place 2D complex 64x64 FFT, 256 threads (32 octets)
template<int DIR>
__device__ __forceinline__ void fft2d64(float2 (*sm)[PITCH])
{
    int unit = threadIdx.x >> 3, lane = threadIdx.x & 7;
    float sn, cs;
    sincospif((float)DIR * (float)lane / 32.0f, &sn, &cs);
    float2 wstep = make_float2(cs, sn);   // exp(DIR * i*pi*lane/32)
    fft64_line<DIR,1>(&sm[unit][0],    lane, wstep);
    fft64_line<DIR,1>(&sm[unit+32][0], lane, wstep);
    __syncthreads();
    fft64_line<DIR,PITCH>(&sm[0][unit],    lane, wstep);
    fft64_line<DIR,PITCH>(&sm[0][unit+32], lane, wstep);
    __syncthreads();
}

// ---------------- 0) gather: x (B,T,H,W,C) -> pair-packed planes d_V --------
__global__ void __launch_bounds__(256) fwd0_kernel(const float* __restrict__ x)
{
    __shared__ float s4[4*2112];        // [h 0..3][w*33 + c]
    int tid = threadIdx.x;
    int bt = blockIdx.x >> 4;           // 0..63
    int hq = blockIdx.x & 15;           // 0..15 (4 rows each)
    const float4* xp = (const float4*)(x + ((size_t)bt*Hh + hq*4)*Ww*Cc);
    #pragma unroll
    for (int i = 0; i < 8; i++) {
        int f = tid + i*256;            // 2048 float4 = 4 rows
        float4 v = xp[f];
        int h = f >> 9;                 // 512 float4 per row
        int r = f & 511;
        int w = r >> 3;                 // 8 float4 per pixel
        int c4 = (r & 7) * 4;
        float* d = &s4[h*2112 + w*33 + c4];
        d[0]=v.x; d[1]=v.y; d[2]=v.z; d[3]=v.w;
    }
    __syncthreads();
    #pragma unroll
    for (int i = 0; i < 16; i++) {
        int o = tid + i*256;            // 4096 = 16p * 4h * 64w
        int p = o >> 8;
        int h = (o >> 6) & 3;
        int w = o & 63;
        float a = s4[h*2112 + w*33 + 2*p];
        float b = s4[h*2112 + w*33 + 2*p + 1];
        d_V[((size_t)(bt*16 + p)*Hh + hq*4 + h)*Ww + w] = make_float2(a, b);
    }
}

// ---------------- 1) fused forward FFT: x pairs (from d_V) + opponent kernels
__global__ void __launch_bounds__(256) fftfwd_kernel(
    const float* __restrict__ ke, const float* __restrict__ ki)
{
    __shared__ float2 sm[64][PITCH];
    int tid = threadIdx.x;

    if (blockIdx.x < 1024) {
        int pi = blockIdx.x;
        int bt = pi >> 4, c = (pi & 15) * 2;
        const float2* vp = d_V + (size_t)pi * (Hh*Ww);
        for (int idx = tid; idx < 4096; idx += 256)
            sm[idx >> 6][idx & 63] = vp[idx];
        __syncthreads();
        fft2d64<-1>(sm);
        if (tid == 0) {
            float2 dc = sm[0][0];       // (sum x_c, sum x_{c+1})
            const float inv = 1.0f / (Hh*Ww);
            d_ctx[bt*Cc + c]     = dc.x * inv;
            d_ctx[bt*Cc + c + 1] = dc.y * inv;
        }
        float2* u0 = d_U + (size_t)(bt*Cc + c) * (Hh*WR);
        float2* u1 = u0 + (Hh*WR);
        for (int idx = tid; idx < Hh*WR; idx += 256) {
            int k = idx / WR, l = idx - k*WR;
            float2 Z1 = sm[k][l];
            float2 Z2 = sm[(64-k)&63][(64-l)&63];
            u0[idx] = make_float2(0.5f*(Z1.x+Z2.x), 0.5f*(Z1.y-Z2.y));   // X_c
            u1[idx] = make_float2(0.5f*(Z1.y+Z2.y), 0.5f*(Z2.x-Z1.x));   // X_{c+1}
        }
    } else {
        int c = blockIdx.x - 1024;      // 0..31
        for (int idx = tid; idx < 4096; idx += 256) {
            int h = idx >> 6, w = idx & 63;
            float ve = 0.f, vi = 0.f;
            if (h >= PAD && h < PAD + KSZ && w >= PAD && w < PAD + KSZ) {
                int o = c*KSZ*KSZ + (h - PAD)*KSZ + (w - PAD);
                ve = ke[o]; vi = ki[o];
            }
            sm[h][w] = make_float2(ve, vi);
        }
        __syncthreads();
        fft2d64<-1>(sm);
        float2* e = d_KE + (size_t)c * (Hh*WR);
        float2* i = d_KI + (size_t)c * (Hh*WR);
        for (int idx = tid; idx < Hh*WR; idx += 256) {
            int k = idx / WR, l = idx - k*WR;
            float2 Z1 = sm[k][l];
            float2 Z2 = sm[(64-k)&63][(64-l)&63];
            e[idx] = make_float2(0.5f*(Z1.x+Z2.x), 0.5f*(Z1.y-Z2.y));
            i[idx] = make_float2(0.5f*(Z1.y+Z2.y), 0.5f*(Z2.x-Z1.x));
        }
    }
}

// ---------------- 2) gates: 4 GEMVs + activations (ctx precomputed) ---------
__global__ void __launch_bounds__(128) gates_kernel(
    const float* __restrict__ wA, const float* __restrict__ bA,
    const float* __restrict__ wD, const float* __restrict__ bD,
    const float* __restrict__ wM, const float* __restrict__ bM,
    const float* __restrict__ wG, const float* __restrict__ bG)
{
    int bt  = blockIdx.x;               // 0..63
    int tid = threadIdx.x;
    __shared__ float ctx[32];
    if (tid < 32) ctx[tid] = d_ctx[bt*Cc + tid];
    __syncthreads();
    int gate = tid >> 5, cc = tid & 31;
    const float* w = (gate == 0) ? wA : (gate == 1) ? wD : (gate == 2) ? wM : wG;
    const float* b = (gate == 0) ? bA : (gate == 1) ? bD : (gate == 2) ? bM : bG;
    float s = b[cc];
    #pragma unroll
    for (int k = 0; k < 32; k++) s = fmaf(ctx[k], w[k*32 + cc], s);
    float v;
    if (gate < 2) v = 1.0f / (1.0f + expf(-s));                 // sigmoid
    else          v = fmaxf(s, 0.f) + log1pf(expf(-fabsf(s)));  // softplus
    d_gates[gate][bt*Cc + cc] = v;
}

// ---------------- 3) per-frequency 2x2 complex recurrence over T ------------
// Batched: 8 independent u-loads in flight (MLP=8), then 8 recurrence steps.
__global__ void __launch_bounds__(256) scan_kernel(const float* __restrict__ decay)
{
    int idx = blockIdx.x * blockDim.x + threadIdx.x;
    if (idx >= Bb*Cc*Hh*WR) return;
    int wr = idx % WR;
    int h  = (idx / WR) % Hh;
    int c  = (idx / (WR*Hh)) % Cc;
    int b  =  idx / (WR*Hh*Cc);

    float dec = fminf(fmaxf(decay[c], 0.1f), 0.99f);
    float2 KE = d_KE[(c*Hh + h)*WR + wr];
    float2 KI = d_KI[(c*Hh + h)*WR + wr];

    const size_t stride = (size_t)Cc*Hh*WR;
    size_t ui   = ((size_t)(b*Tt*Cc + c)*Hh + h)*WR + wr;
    int    gidx = (b*Tt)*Cc + c;

    float2 sx = make_float2(0.f, 0.f), sy = make_float2(0.f, 0.f);
    #pragma unroll
    for (int tb = 0; tb < Tt/8; tb++) {
        float2 ub[8];
        #pragma unroll
        for (int j = 0; j < 8; j++) ub[j] = d_U[ui + (size_t)j*stride];   // 8 loads in flight
        #pragma unroll
        for (int j = 0; j < 8; j++) {
            float alpha = d_gates[0][gidx];
            float delta = d_gates[1][gidx];
            float mu    = d_gates[2][gidx];
            float gamma = d_gates[3][gidx];
            float  axx = dec * alpha;
            float  ayy = dec * delta;
            float2 axy = make_float2(-KI.x * mu,    -KI.y * mu);
            float2 ayx = make_float2( KE.x * gamma,  KE.y * gamma);

            float2 u = ub[j];
            float2 nx, ny;
            nx.x = fmaf(axx, sx.x, fmaf(axy.x, sy.x, fmaf(-axy.y, sy.y, u.x)));
            nx.y = fmaf(axx, sx.y, fmaf(axy.x, sy.y, fmaf( axy.y, sy.x, u.y)));
            ny.x = fmaf(ayx.x, sx.x, fmaf(-ayx.y, sx.y, fmaf(ayy, sy.x, 1e-10f)));
            ny.y = fmaf(ayx.x, sx.y, fmaf( ayx.y, sx.x, ayy * sy.y));
            sx = nx; sy = ny;
            d_U[ui + (size_t)j*stride] = sy;          // Y_hat overwrites U_hat
            gidx += Cc;
        }
        ui += (size_t)8*stride;
    }
}

// ---------------- 4) irfft2 per pair -> d_V planes (coalesced) ---------------
__global__ void __launch_bounds__(256) inv1_kernel()
{
    __shared__ float2 sm[64][PITCH];
    int tid = threadIdx.x;

    int pi = blockIdx.x;                // 0..1023
    int bt = pi >> 4, c = (pi & 15) * 2;
    const float2* y0 = d_U + (size_t)(bt*Cc + c) * (Hh*WR);
    const float2* y1 = y0 + (Hh*WR);

    // Z[k][l] = Yc + i*Yc1 for l<=32
    for (int idx = tid; idx < Hh*WR; idx += 256) {
        int k = idx / WR, l = idx - k*WR;
        float2 a = y0[idx], b = y1[idx];
        sm[k][l] = make_float2(a.x - b.y, a.y + b.x);
    }
    // Hermitian fill: l in 33..63
    for (int idx = tid; idx < 64*31; idx += 256) {
        int k = idx / 31, l = 33 + (idx - (idx/31)*31);
        int kk = (64 - k) & 63;
        int src = kk*WR + (64 - l);
        float2 a = y0[src], b = y1[src];
        sm[k][l] = make_float2(a.x + b.y, b.x - a.y);
    }
    __syncthreads();
    fft2d64<+1>(sm);
    float2* vp = d_V + (size_t)pi * (Hh*Ww);
    const float sc = 1.0f / (Hh*Ww);
    for (int idx = tid; idx < 4096; idx += 256) {
        float2 z = sm[idx >> 6][idx & 63];
        vp[idx] = make_float2(z.x * sc, z.y * sc);
    }
}

// ---------------- 5) scatter: d_V planes -> out (B,T,H,W,C), coalesced ------
__global__ void __launch_bounds__(256) inv2_kernel(float* __restrict__ out)
{
    __shared__ float s4[4*2112];
    int tid = threadIdx.x;
    int bt = blockIdx.x >> 4;
    int hq = blockIdx.x & 15;
    #pragma unroll
    for (int i = 0; i < 16; i++) {
        int o = tid + i*256;            // 4096
        int p = o >> 8;
        int h = (o >> 6) & 3;
        int w = o & 63;
        float2 v = d_V[((size_t)(bt*16 + p)*Hh + hq*4 + h)*Ww + w];
        s4[h*2112 + w*33 + 2*p]     = v.x;
        s4[h*2112 + w*33 + 2*p + 1] = v.y;
    }
    __syncthreads();
    float4* op = (float4*)(out + ((size_t)bt*Hh + hq*4)*Ww*Cc);
    #pragma unroll
    for (int i = 0; i < 8; i++) {
        int f = tid + i*256;            // 2048 float4 = 4 rows
        int h = f >> 9;
        int r = f & 511;
        int w = r >> 3;
        int c4 = (r & 7) * 4;
        const float* s = &s4[h*2112 + w*33 + c4];
        op[f] = make_float4(s[0], s[1], s[2], s[3]);
    }
}

// ---------------------------------------------------------------------------
extern "C" void kernel_launch(void* const* d_in, const int* in_sizes, int n_in,
                              void* d_out, int out_size)
{
    const float* x     = (const float*)d_in[0];
    const float* wA    = (const float*)d_in[1];
    const float* bA    = (const float*)d_in[2];
    const float* wD    = (const float*)d_in[3];
    const float* bD    = (const float*)d_in[4];
    const float* wM    = (const float*)d_in[5];
    const float* bM    = (const float*)d_in[6];
    const float* wG    = (const float*)d_in[7];
    const float* bG    = (const float*)d_in[8];
    const float* decay = (const float*)d_in[9];
    const float* ke    = (const float*)d_in[10];
    const float* ki    = (const float*)d_in[11];
    float* out = (float*)d_out;

    fwd0_kernel<<<Bb*Tt*16, 256>>>(x);
    fftfwd_kernel<<<Bb*Tt*Cc/2 + Cc, 256>>>(ke, ki);
    gates_kernel<<<Bb*Tt, 128>>>(wA, bA, wD, bD, wM, bM, wG, bG);
    int nScan = Bb*Cc*Hh*WR;
    scan_kernel<<<(nScan + 255)/256, 256>>>(decay);
    inv1_kernel<<<Bb*Tt*Cc/2, 256>>>();
    inv2_kernel<<<Bb*Tt*16, 256>>>(out);
}

// round 15
// speedup vs baseline: 1.2128x; 1.2128x over previous
#include <cuda_runtime.h>
#include <math.h>

#define Bb  2
#define Tt  32
#define Hh  64
#define Ww  64
#define Cc  32
#define KSZ 15
#define WR  33          // W/2 + 1
#define PAD 24          // (64-15)//2
#define PITCH 70        // smem row pitch in float2

// ---------------- scratch (device globals: allocation-free) ----------------
__device__ float2 d_U[Bb*Tt*Cc*Hh*WR];   // U_hat (scan input, read-only there)
__device__ float2 d_Y[Bb*Tt*Cc*Hh*WR];   // Y_hat (scan output; no aliasing with d_U)
__device__ float2 d_V[Bb*Tt*(Cc/2)*Hh*Ww]; // pair-packed planes (fwd staging / inv result)
__device__ float2 d_KE[Cc*Hh*WR];
__device__ float2 d_KI[Cc*Hh*WR];
__device__ float  d_gates[4][Bb*Tt*Cc];  // alpha, delta, mu, gamma
__device__ float  d_ctx[Bb*Tt*Cc];       // spatial means (from FFT DC bin)

// ---------------- complex helpers ----------------
__device__ __forceinline__ float2 cadd(float2 a, float2 b){ return make_float2(a.x+b.x, a.y+b.y); }
__device__ __forceinline__ float2 csub(float2 a, float2 b){ return make_float2(a.x-b.x, a.y-b.y); }
__device__ __forceinline__ float2 cmul(float2 a, float2 b){
    return make_float2(a.x*b.x - a.y*b.y, a.x*b.y + a.y*b.x);
}

// 8-pt DIF FFT in registers. DIR=-1 fwd, +1 inv. Output bit-reversed:
// X[k] = v[rev(k)], rev = {0,4,2,6,1,5,3,7}.
template<int DIR>
__device__ __forceinline__ void fft8r(float2 v[8]) {
    const float s = 0.70710678118654752f;
    float2 t0=csub(v[0],v[4]), t1=csub(v[1],v[5]), t2=csub(v[2],v[6]), t3=csub(v[3],v[7]);
    v[0]=cadd(v[0],v[4]); v[1]=cadd(v[1],v[5]); v[2]=cadd(v[2],v[6]); v[3]=cadd(v[3],v[7]);
    v[4]=t0;
    v[5]=cmul(t1, make_float2(s, (float)DIR*s));
    v[6]=make_float2(-(float)DIR*t2.y, (float)DIR*t2.x);
    v[7]=cmul(t3, make_float2(-s, (float)DIR*s));
    #pragma unroll
    for (int o=0;o<8;o+=4){
        float2 a=v[o],   b=v[o+2]; v[o]  =cadd(a,b); float2 d0=csub(a,b);
        float2 c=v[o+1], d=v[o+3]; v[o+1]=cadd(c,d); float2 d1=csub(c,d);
        v[o+2]=d0;
        v[o+3]=make_float2(-(float)DIR*d1.y, (float)DIR*d1.x);
    }
    #pragma unroll
    for (int o=0;o<8;o+=2){
        float2 a=v[o], b=v[o+1]; v[o]=cadd(a,b); v[o+1]=csub(a,b);
    }
}

// 64-pt FFT over one line, by an 8-lane octet. smem touched only at load+store;
// the middle transpose is register-resident via shfl_xor within the octet.
template<int DIR, int STRIDE>
__device__ __forceinline__ void fft64_line(float2* base, int lane, float2 wstep)
{
    constexpr int rv[8] = {0,4,2,6,1,5,3,7};
    float2 v[8];
    #pragma unroll
    for (int n=0;n<8;n++) v[n] = base[(8*n+lane)*STRIDE];
    fft8r<DIR>(v);
    float2 w[8];
    w[0] = v[0];                       // rv[0]=0, twiddle^0
    float2 t = wstep;
    w[1] = cmul(v[rv[1]], t);
    #pragma unroll
    for (int k=2;k<8;k++){ t = cmul(t, wstep); w[k] = cmul(v[rv[k]], t); }
    // 8x8 octet transpose (Eklundh): out[reg r][lane l] = in[reg l][lane r]
    #pragma unroll
    for (int s=1;s<8;s<<=1){
        #pragma unroll
        for (int k=0;k<8;k++){
            if ((k & s) == 0){
                float2 give = (lane & s) ? w[k] : w[k|s];
                float2 got;
                got.x = __shfl_xor_sync(0xffffffffu, give.x, s);
                got.y = __shfl_xor_sync(0xffffffffu, give.y, s);
                if (lane & s) w[k] = got; else w[k|s] = got;
            }
        }
    }
    fft8r<DIR>(w);
    #pragma unroll
    for (int k=0;k<8;k++) base[(8*k+lane)*STRIDE] = w[rv[k]];
}

// full in-place 2D complex 64x64 FFT, 256 threads (32 octets)
template<int DIR>
__device__ __forceinline__ void fft2d64(float2 (*sm)[PITCH])
{
    int unit = threadIdx.x >> 3, lane = threadIdx.x & 7;
    float sn, cs;
    sincospif((float)DIR * (float)lane / 32.0f, &sn, &cs);
    float2 wstep = make_float2(cs, sn);   // exp(DIR * i*pi*lane/32)
    fft64_line<DIR,1>(&sm[unit][0],    lane, wstep);
    fft64_line<DIR,1>(&sm[unit+32][0], lane, wstep);
    __syncthreads();
    fft64_line<DIR,PITCH>(&sm[0][unit],    lane, wstep);
    fft64_line<DIR,PITCH>(&sm[0][unit+32], lane, wstep);
    __syncthreads();
}

// ---------------- 0) gather: x (B,T,H,W,C) -> pair-packed planes d_V --------
__global__ void __launch_bounds__(256) fwd0_kernel(const float* __restrict__ x)
{
    __shared__ float s4[4*2112];        // [h 0..3][w*33 + c]
    int tid = threadIdx.x;
    int bt = blockIdx.x >> 4;           // 0..63
    int hq = blockIdx.x & 15;           // 0..15 (4 rows each)
    const float4* xp = (const float4*)(x + ((size_t)bt*Hh + hq*4)*Ww*Cc);
    #pragma unroll
    for (int i = 0; i < 8; i++) {
        int f = tid + i*256;            // 2048 float4 = 4 rows
        float4 v = xp[f];
        int h = f >> 9;                 // 512 float4 per row
        int r = f & 511;
        int w = r >> 3;                 // 8 float4 per pixel
        int c4 = (r & 7) * 4;
        float* d = &s4[h*2112 + w*33 + c4];
        d[0]=v.x; d[1]=v.y; d[2]=v.z; d[3]=v.w;
    }
    __syncthreads();
    #pragma unroll
    for (int i = 0; i < 16; i++) {
        int o = tid + i*256;            // 4096 = 16p * 4h * 64w
        int p = o >> 8;
        int h = (o >> 6) & 3;
        int w = o & 63;
        float a = s4[h*2112 + w*33 + 2*p];
        float b = s4[h*2112 + w*33 + 2*p + 1];
        d_V[((size_t)(bt*16 + p)*Hh + hq*4 + h)*Ww + w] = make_float2(a, b);
    }
}

// ---------------- 1) fused forward FFT: x pairs (from d_V) + opponent kernels
__global__ void __launch_bounds__(256) fftfwd_kernel(
    const float* __restrict__ ke, const float* __restrict__ ki)
{
    __shared__ float2 sm[64][PITCH];
    int tid = threadIdx.x;

    if (blockIdx.x < 1024) {
        int pi = blockIdx.x;
        int bt = pi >> 4, c = (pi & 15) * 2;
        const float2* vp = d_V + (size_t)pi * (Hh*Ww);
        for (int idx = tid; idx < 4096; idx += 256)
            sm[idx >> 6][idx & 63] = vp[idx];
        __syncthreads();
        fft2d64<-1>(sm);
        if (tid == 0) {
            float2 dc = sm[0][0];       // (sum x_c, sum x_{c+1})
            const float inv = 1.0f / (Hh*Ww);
            d_ctx[bt*Cc + c]     = dc.x * inv;
            d_ctx[bt*Cc + c + 1] = dc.y * inv;
        }
        float2* u0 = d_U + (size_t)(bt*Cc + c) * (Hh*WR);
        float2* u1 = u0 + (Hh*WR);
        for (int idx = tid; idx < Hh*WR; idx += 256) {
            int k = idx / WR, l = idx - k*WR;
            float2 Z1 = sm[k][l];
            float2 Z2 = sm[(64-k)&63][(64-l)&63];
            u0[idx] = make_float2(0.5f*(Z1.x+Z2.x), 0.5f*(Z1.y-Z2.y));   // X_c
            u1[idx] = make_float2(0.5f*(Z1.y+Z2.y), 0.5f*(Z2.x-Z1.x));   // X_{c+1}
        }
    } else {
        int c = blockIdx.x - 1024;      // 0..31
        for (int idx = tid; idx < 4096; idx += 256) {
            int h = idx >> 6, w = idx & 63;
            float ve = 0.f, vi = 0.f;
            if (h >= PAD && h < PAD + KSZ && w >= PAD && w < PAD + KSZ) {
                int o = c*KSZ*KSZ + (h - PAD)*KSZ + (w - PAD);
                ve = ke[o]; vi = ki[o];
            }
            sm[h][w] = make_float2(ve, vi);
        }
        __syncthreads();
        fft2d64<-1>(sm);
        float2* e = d_KE + (size_t)c * (Hh*WR);
        float2* i = d_KI + (size_t)c * (Hh*WR);
        for (int idx = tid; idx < Hh*WR; idx += 256) {
            int k = idx / WR, l = idx - k*WR;
            float2 Z1 = sm[k][l];
            float2 Z2 = sm[(64-k)&63][(64-l)&63];
            e[idx] = make_float2(0.5f*(Z1.x+Z2.x), 0.5f*(Z1.y-Z2.y));
            i[idx] = make_float2(0.5f*(Z1.y+Z2.y), 0.5f*(Z2.x-Z1.x));
        }
    }
}

// ---------------- 2) gates: 4 GEMVs + activations (ctx precomputed) ---------
__global__ void __launch_bounds__(128) gates_kernel(
    const float* __restrict__ wA, const float* __restrict__ bA,
    const float* __restrict__ wD, const float* __restrict__ bD,
    const float* __restrict__ wM, const float* __restrict__ bM,
    const float* __restrict__ wG, const float* __restrict__ bG)
{
    int bt  = blockIdx.x;               // 0..63
    int tid = threadIdx.x;
    __shared__ float ctx[32];
    if (tid < 32) ctx[tid] = d_ctx[bt*Cc + tid];
    __syncthreads();
    int gate = tid >> 5, cc = tid & 31;
    const float* w = (gate == 0) ? wA : (gate == 1) ? wD : (gate == 2) ? wM : wG;
    const float* b = (gate == 0) ? bA : (gate == 1) ? bD : (gate == 2) ? bM : bG;
    float s = b[cc];
    #pragma unroll
    for (int k = 0; k < 32; k++) s = fmaf(ctx[k], w[k*32 + cc], s);
    float v;
    if (gate < 2) v = 1.0f / (1.0f + expf(-s));                 // sigmoid
    else          v = fmaxf(s, 0.f) + log1pf(expf(-fabsf(s)));  // softplus
    d_gates[gate][bt*Cc + cc] = v;
}

// ---------------- 3) per-frequency 2x2 complex recurrence over T ------------
// Reads d_U, writes d_Y (distinct arrays -> compiler can hoist loads freely).
__global__ void __launch_bounds__(256) scan_kernel(const float* __restrict__ decay)
{
    int idx = blockIdx.x * blockDim.x + threadIdx.x;
    if (idx >= Bb*Cc*Hh*WR) return;
    int wr = idx % WR;
    int h  = (idx / WR) % Hh;
    int c  = (idx / (WR*Hh)) % Cc;
    int b  =  idx / (WR*Hh*Cc);

    float dec = fminf(fmaxf(decay[c], 0.1f), 0.99f);
    float2 KE = d_KE[(c*Hh + h)*WR + wr];
    float2 KI = d_KI[(c*Hh + h)*WR + wr];

    const size_t stride = (size_t)Cc*Hh*WR;
    size_t ui   = ((size_t)(b*Tt*Cc + c)*Hh + h)*WR + wr;
    int    gidx = (b*Tt)*Cc + c;

    float2 sx = make_float2(0.f, 0.f), sy = make_float2(0.f, 0.f);
    #pragma unroll 4
    for (int t = 0; t < Tt; t++) {
        float2 u = d_U[ui];
        float alpha = d_gates[0][gidx];
        float delta = d_gates[1][gidx];
        float mu    = d_gates[2][gidx];
        float gamma = d_gates[3][gidx];
        float  axx = dec * alpha;
        float  ayy = dec * delta;
        float2 axy = make_float2(-KI.x * mu,    -KI.y * mu);
        float2 ayx = make_float2( KE.x * gamma,  KE.y * gamma);

        float2 nx, ny;
        nx.x = fmaf(axx, sx.x, fmaf(axy.x, sy.x, fmaf(-axy.y, sy.y, u.x)));
        nx.y = fmaf(axx, sx.y, fmaf(axy.x, sy.y, fmaf( axy.y, sy.x, u.y)));
        ny.x = fmaf(ayx.x, sx.x, fmaf(-ayx.y, sx.y, fmaf(ayy, sy.x, 1e-10f)));
        ny.y = fmaf(ayx.x, sx.y, fmaf( ayx.y, sx.x, ayy * sy.y));
        sx = nx; sy = ny;
        d_Y[ui] = sy;                    // separate output array: no aliasing
        ui += stride; gidx += Cc;
    }
}

// ---------------- 4) irfft2 per pair -> d_V planes (coalesced) ---------------
__global__ void __launch_bounds__(256) inv1_kernel()
{
    __shared__ float2 sm[64][PITCH];
    int tid = threadIdx.x;

    int pi = blockIdx.x;                // 0..1023
    int bt = pi >> 4, c = (pi & 15) * 2;
    const float2* y0 = d_Y + (size_t)(bt*Cc + c) * (Hh*WR);
    const float2* y1 = y0 + (Hh*WR);

    // Z[k][l] = Yc + i*Yc1 for l<=32
    for (int idx = tid; idx < Hh*WR; idx += 256) {
        int k = idx / WR, l = idx - k*WR;
        float2 a = y0[idx], b = y1[idx];
        sm[k][l] = make_float2(a.x - b.y, a.y + b.x);
    }
    // Hermitian fill: l in 33..63
    for (int idx = tid; idx < 64*31; idx += 256) {
        int k = idx / 31, l = 33 + (idx - (idx/31)*31);
        int kk = (64 - k) & 63;
        int src = kk*WR + (64 - l);
        float2 a = y0[src], b = y1[src];
        sm[k][l] = make_float2(a.x + b.y, b.x - a.y);
    }
    __syncthreads();
    fft2d64<+1>(sm);
    float2* vp = d_V + (size_t)pi * (Hh*Ww);
    const float sc = 1.0f / (Hh*Ww);
    for (int idx = tid; idx < 4096; idx += 256) {
        float2 z = sm[idx >> 6][idx & 63];
        vp[idx] = make_float2(z.x * sc, z.y * sc);
    }
}

// ---------------- 5) scatter: d_V planes -> out (B,T,H,W,C), coalesced ------
__global__ void __launch_bounds__(256) inv2_kernel(float* __restrict__ out)
{
    __shared__ float s4[4*2112];
    int tid = threadIdx.x;
    int bt = blockIdx.x >> 4;
    int hq = blockIdx.x & 15;
    #pragma unroll
    for (int i = 0; i < 16; i++) {
        int o = tid + i*256;            // 4096
        int p = o >> 8;
        int h = (o >> 6) & 3;
        int w = o & 63;
        float2 v = d_V[((size_t)(bt*16 + p)*Hh + hq*4 + h)*Ww + w];
        s4[h*2112 + w*33 + 2*p]     = v.x;
        s4[h*2112 + w*33 + 2*p + 1] = v.y;
    }
    __syncthreads();
    float4* op = (float4*)(out + ((size_t)bt*Hh + hq*4)*Ww*Cc);
    #pragma unroll
    for (int i = 0; i < 8; i++) {
        int f = tid + i*256;            // 2048 float4 = 4 rows
        int h = f >> 9;
        int r = f & 511;
        int w = r >> 3;
        int c4 = (r & 7) * 4;
        const float* s = &s4[h*2112 + w*33 + c4];
        op[f] = make_float4(s[0], s[1], s[2], s[3]);
    }
}

// ---------------------------------------------------------------------------
extern "C" void kernel_launch(void* const* d_in, const int* in_sizes, int n_in,
                              void* d_out, int out_size)
{
    const float* x     = (const float*)d_in[0];
    const float* wA    = (const float*)d_in[1];
    const float* bA    = (const float*)d_in[2];
    const float* wD    = (const float*)d_in[3];
    const float* bD    = (const float*)d_in[4];
    const float* wM    = (const float*)d_in[5];
    const float* bM    = (const float*)d_in[6];
    const float* wG    = (const float*)d_in[7];
    const float* bG    = (const float*)d_in[8];
    const float* decay = (const float*)d_in[9];
    const float* ke    = (const float*)d_in[10];
    const float* ki    = (const float*)d_in[11];
    float* out = (float*)d_out;

    fwd0_kernel<<<Bb*Tt*16, 256>>>(x);
    fftfwd_kernel<<<Bb*Tt*Cc/2 + Cc, 256>>>(ke, ki);
    gates_kernel<<<Bb*Tt, 128>>>(wA, bA, wD, bD, wM, bM, wG, bG);
    int nScan = Bb*Cc*Hh*WR;
    scan_kernel<<<(nScan + 255)/256, 256>>>(decay);
    inv1_kernel<<<Bb*Tt*Cc/2, 256>>>();
    inv2_kernel<<<Bb*Tt*16, 256>>>(out);
}